// round 2
// baseline (speedup 1.0000x reference)
#include <cuda_runtime.h>

#define PTS 131072
#define SVOX 131072
#define EPSV 1e-5f
#define NEGINF (-3.402823466e+38f)

// ---------------- static device scratch (no allocations allowed) ----------------
__device__ float g_Y1[PTS * 64];          //  33.5 MB
__device__ float g_Y2[PTS * 128];         //  67 MB
__device__ float g_Y3[PTS * 256];         // 134 MB
__device__ float g_pooled[67108864];      // 268 MB  [SVOX, 512]
__device__ int           g_keys[PTS];
__device__ unsigned char g_occ[SVOX];
__device__ float g_part[256 * 512];       // stats partials: [256 blocks][2*C], C<=256
__device__ float g_scale[4][256];
__device__ float g_shift[4][256];

// ---------------- helpers ----------------
__device__ __forceinline__ void atomicMaxF(float* addr, float v) {
    if (v >= 0.f) atomicMax((int*)addr, __float_as_int(v));
    else          atomicMin((unsigned int*)addr, __float_as_uint(v));
}

// ---------------- init pooled + occ ----------------
__global__ void init_kernel() {
    unsigned i = blockIdx.x * blockDim.x + threadIdx.x;
    unsigned stride = gridDim.x * blockDim.x;
    float4 neg = make_float4(NEGINF, NEGINF, NEGINF, NEGINF);
    float4* p = (float4*)g_pooled;
    for (unsigned j = i; j < 16777216u; j += stride) p[j] = neg;
    for (unsigned j = i; j < SVOX; j += stride) g_occ[j] = 0;
}

// ---------------- keys + occupancy ----------------
__global__ void keys_kernel(const int* __restrict__ xy) {
    int p = blockIdx.x * blockDim.x + threadIdx.x;
    if (p < PTS) {
        int x = xy[2 * p], y = xy[2 * p + 1];
        int key = ((p >> 16) << 16) | (x << 8) | y;   // batch*65536 + x*256 + y
        g_keys[p] = key;
        g_occ[key] = 1;
    }
}

// ---------------- column stats: partial sums over fixed row ranges (deterministic) ----------------
template <int C>
__global__ void __launch_bounds__(256) stats_part(const float* __restrict__ Y) {
    const int PER = 256 / C;                  // threads per column
    int t = threadIdx.x;
    int c = t % C, sl = t / C;
    int r0 = blockIdx.x * (PTS / 256);        // 512 rows per block
    float s = 0.f, q = 0.f;
    for (int r = r0 + sl; r < r0 + PTS / 256; r += PER) {
        float v = Y[(size_t)r * C + c];
        s += v; q += v * v;
    }
    __shared__ float ss[256], sq[256];
    ss[t] = s; sq[t] = q;
    __syncthreads();
    if (sl == 0) {
        for (int i = 1; i < PER; i++) { s += ss[c + i * C]; q += sq[c + i * C]; }
        g_part[blockIdx.x * 2 * C + c]     = s;
        g_part[blockIdx.x * 2 * C + C + c] = q;
    }
}

template <int C>
__global__ void stats_fin(int L, const float* __restrict__ gam, const float* __restrict__ bet) {
    int c = threadIdx.x;
    if (c >= C) return;
    double s = 0.0, q = 0.0;
    for (int b = 0; b < 256; b++) {
        s += (double)g_part[b * 2 * C + c];
        q += (double)g_part[b * 2 * C + C + c];
    }
    float mean = (float)(s / (double)PTS);
    float var  = (float)(q / (double)PTS) - mean * mean;
    float sc   = gam[c] * rsqrtf(var + EPSV);
    g_scale[L][c] = sc;
    g_shift[L][c] = bet[c] - mean * sc;
}

// ---------------- GEMM1: Y1[P,64] = (X*s0+b0) @ W1[8,64] ----------------
__global__ void __launch_bounds__(256) gemm1(const float* __restrict__ X, const float* __restrict__ W) {
    __shared__ float Xs[128][9];
    __shared__ float Ws[8][64];
    int tid = threadIdx.x;
    int m0 = blockIdx.x * 128;

    int row = tid >> 1, c4 = (tid & 1) * 4;
    float4 xv = *(const float4*)(X + (size_t)(m0 + row) * 8 + c4);
    float xa[4] = {xv.x, xv.y, xv.z, xv.w};
#pragma unroll
    for (int j = 0; j < 4; j++)
        Xs[row][c4 + j] = xa[j] * g_scale[0][c4 + j] + g_shift[0][c4 + j];
    if (tid < 128) {
        int r = tid >> 4, cc = (tid & 15) * 4;
        *(float4*)&Ws[r][cc] = *(const float4*)(W + r * 64 + cc);
    }
    __syncthreads();

    int tx = tid & 15, ty = tid >> 4;
    float acc[8][4] = {};
#pragma unroll
    for (int k = 0; k < 8; k++) {
        float4 bv = *(float4*)&Ws[k][tx * 4];
        float b[4] = {bv.x, bv.y, bv.z, bv.w};
#pragma unroll
        for (int i = 0; i < 8; i++) {
            float a = Xs[ty * 8 + i][k];
#pragma unroll
            for (int j = 0; j < 4; j++) acc[i][j] += a * b[j];
        }
    }
#pragma unroll
    for (int i = 0; i < 8; i++) {
        float4 o = make_float4(acc[i][0], acc[i][1], acc[i][2], acc[i][3]);
        *(float4*)&g_Y1[(size_t)(m0 + ty * 8 + i) * 64 + tx * 4] = o;
    }
}

// ---------------- main SGEMM: 128x128 block, 8x8 thread tile, BK=8 ----------------
// Y[M,N] = act(X)[M,K] @ W[K,N];   act(x) = [relu]( x*scale[L] + shift[L] )
// SCATTER: atomicMax into g_pooled[key*512 + n] instead of storing Y.
template <int K, int N, bool RELU, bool SCATTER>
__global__ void __launch_bounds__(256) sgemm(const float* __restrict__ X, const float* __restrict__ W,
                                             float* __restrict__ Y, int L) {
    __shared__ float As[8][128];
    __shared__ float Bs[8][128];
    int tid = threadIdx.x;
    int m0 = blockIdx.x * 128;
    int n0 = blockIdx.y * 128;
    int tx = tid & 15, ty = tid >> 4;
    const int aRow = tid >> 1, aCol = (tid & 1) * 4;
    const int bRow = tid >> 5, bCol = (tid & 31) * 4;

    float acc[8][8] = {};

    for (int kc = 0; kc < K; kc += 8) {
        float4 xv = *(const float4*)(X + (size_t)(m0 + aRow) * K + kc + aCol);
        float xa[4] = {xv.x, xv.y, xv.z, xv.w};
#pragma unroll
        for (int j = 0; j < 4; j++) {
            float v = xa[j] * g_scale[L][kc + aCol + j] + g_shift[L][kc + aCol + j];
            if (RELU) v = fmaxf(v, 0.f);
            As[aCol + j][aRow] = v;
        }
        *(float4*)&Bs[bRow][bCol] = *(const float4*)(W + (size_t)(kc + bRow) * N + n0 + bCol);
        __syncthreads();
#pragma unroll
        for (int k = 0; k < 8; k++) {
            float a[8], b[8];
            *(float4*)&a[0] = *(float4*)&As[k][ty * 4];
            *(float4*)&a[4] = *(float4*)&As[k][64 + ty * 4];
            *(float4*)&b[0] = *(float4*)&Bs[k][tx * 4];
            *(float4*)&b[4] = *(float4*)&Bs[k][64 + tx * 4];
#pragma unroll
            for (int i = 0; i < 8; i++)
#pragma unroll
                for (int j = 0; j < 8; j++) acc[i][j] += a[i] * b[j];
        }
        __syncthreads();
    }

    if (!SCATTER) {
#pragma unroll
        for (int i = 0; i < 8; i++) {
            int m = m0 + ((i < 4) ? (ty * 4 + i) : (64 + ty * 4 + i - 4));
            float4 o0 = make_float4(acc[i][0], acc[i][1], acc[i][2], acc[i][3]);
            float4 o1 = make_float4(acc[i][4], acc[i][5], acc[i][6], acc[i][7]);
            *(float4*)&Y[(size_t)m * N + n0 + tx * 4]      = o0;
            *(float4*)&Y[(size_t)m * N + n0 + 64 + tx * 4] = o1;
        }
    } else {
#pragma unroll
        for (int i = 0; i < 8; i++) {
            int m = m0 + ((i < 4) ? (ty * 4 + i) : (64 + ty * 4 + i - 4));
            int key = g_keys[m];
            float* row = g_pooled + (size_t)key * 512;
#pragma unroll
            for (int j = 0; j < 8; j++) {
                int n = n0 + ((j < 4) ? (tx * 4 + j) : (64 + tx * 4 + j - 4));
                atomicMaxF(row + n, acc[i][j]);
            }
        }
    }
}

// ---------------- output: comp = relu(pooled @ Wc) masked by occ, transposed write ----------------
// block: 256 threads, 32 voxels; k staged in 128-wide smem chunks.
__global__ void __launch_bounds__(256) outker(const float* __restrict__ Wc, float* __restrict__ out) {
    __shared__ float sm[32][129];
    int tid = threadIdx.x;
    int vbase = blockIdx.x * 32;
    int vi = tid & 31, cg = tid >> 5;           // vi: voxel-in-block, cg: 4-col group (0..7)
    float acc[4] = {0.f, 0.f, 0.f, 0.f};

    for (int kc = 0; kc < 512; kc += 128) {
#pragma unroll
        for (int i = 0; i < 4; i++) {
            int q = tid + 256 * i;              // 0..1023
            int row = q >> 5, col = (q & 31) * 4;
            float4 v = *(const float4*)(g_pooled + (size_t)(vbase + row) * 512 + kc + col);
            sm[row][col + 0] = v.x; sm[row][col + 1] = v.y;
            sm[row][col + 2] = v.z; sm[row][col + 3] = v.w;
        }
        __syncthreads();
#pragma unroll 4
        for (int k = 0; k < 128; k++) {
            float p = sm[vi][k];
            float4 w = *(const float4*)(Wc + (size_t)(kc + k) * 32 + cg * 4);
            acc[0] += p * w.x; acc[1] += p * w.y; acc[2] += p * w.z; acc[3] += p * w.w;
        }
        __syncthreads();
    }

    int v = vbase + vi;
    bool oc = g_occ[v] != 0;
    int b = v >> 16, hw = v & 65535;
#pragma unroll
    for (int j = 0; j < 4; j++) {
        float r = oc ? fmaxf(acc[j], 0.f) : 0.f;
        out[(size_t)(b * 32 + cg * 4 + j) * 65536 + hw] = r;
    }
}

// ---------------- launcher ----------------
extern "C" void kernel_launch(void* const* d_in, const int* in_sizes, int n_in,
                              void* d_out, int out_size) {
    (void)in_sizes; (void)n_in; (void)out_size;
    const float* pt_fea = (const float*)d_in[0];
    const float* bn0_g  = (const float*)d_in[1];
    const float* bn0_b  = (const float*)d_in[2];
    const float* W1     = (const float*)d_in[3];
    const float* bn1_g  = (const float*)d_in[4];
    const float* bn1_b  = (const float*)d_in[5];
    const float* W2     = (const float*)d_in[6];
    const float* bn2_g  = (const float*)d_in[7];
    const float* bn2_b  = (const float*)d_in[8];
    const float* W3     = (const float*)d_in[9];
    const float* bn3_g  = (const float*)d_in[10];
    const float* bn3_b  = (const float*)d_in[11];
    const float* W4     = (const float*)d_in[12];
    const float* Wc     = (const float*)d_in[13];
    const int*   xy     = (const int*)d_in[14];
    float* out = (float*)d_out;

    float *Y1p, *Y2p, *Y3p;
    cudaGetSymbolAddress((void**)&Y1p, g_Y1);
    cudaGetSymbolAddress((void**)&Y2p, g_Y2);
    cudaGetSymbolAddress((void**)&Y3p, g_Y3);

    init_kernel<<<2048, 256>>>();
    keys_kernel<<<512, 256>>>(xy);

    stats_part<8><<<256, 256>>>(pt_fea);
    stats_fin<8><<<1, 256>>>(0, bn0_g, bn0_b);
    gemm1<<<1024, 256>>>(pt_fea, W1);

    stats_part<64><<<256, 256>>>(Y1p);
    stats_fin<64><<<1, 256>>>(1, bn1_g, bn1_b);
    sgemm<64, 128, true, false><<<dim3(1024, 1), 256>>>(Y1p, W2, Y2p, 1);

    stats_part<128><<<256, 256>>>(Y2p);
    stats_fin<128><<<1, 256>>>(2, bn2_g, bn2_b);
    sgemm<128, 256, true, false><<<dim3(1024, 2), 256>>>(Y2p, W3, Y3p, 2);

    stats_part<256><<<256, 256>>>(Y3p);
    stats_fin<256><<<1, 256>>>(3, bn3_g, bn3_b);
    sgemm<256, 512, true, true><<<dim3(1024, 4), 256>>>(Y3p, W4, nullptr, 3);

    outker<<<4096, 256>>>(Wc, out);
}

// round 5
// speedup vs baseline: 1.7115x; 1.7115x over previous
#include <cuda_runtime.h>
#include <cstdint>

#define PTS 131072
#define SVOX 131072
#define EPSV 1e-5f
#define NEGINF (-3.402823466e+38f)

// ---------------- static device scratch ----------------
__device__ float g_Y1[PTS * 64];
__device__ float g_Y2[PTS * 128];
__device__ float g_Y3[PTS * 256];
__device__ float g_pooled[67108864];      // [SVOX, 512]
__device__ int   g_keys[PTS];
__device__ int   g_cnt[SVOX];
__device__ float g_part[256 * 512];
__device__ float g_scale[4][256];
__device__ float g_shift[4][256];
__device__ float g_Wr2[64 * 128];         // tf32-rounded W2 [K][N]
__device__ float g_Wr3[128 * 256];
__device__ float g_Wr4[256 * 512];

// ---------------- helpers ----------------
__device__ __forceinline__ uint32_t smem_u32(const void* p) {
    uint32_t a;
    asm("{ .reg .u64 t; cvta.to.shared.u64 t, %1; cvt.u32.u64 %0, t; }" : "=r"(a) : "l"(p));
    return a;
}
__device__ __forceinline__ float to_tf32(float x) {
    uint32_t o; asm("cvt.rna.tf32.f32 %0, %1;" : "=r"(o) : "f"(x));
    return __uint_as_float(o);
}
__device__ __forceinline__ void cp16(uint32_t saddr, const void* g) {
    asm volatile("cp.async.cg.shared.global [%0], [%1], 16;" :: "r"(saddr), "l"(g));
}
#define CP_COMMIT() asm volatile("cp.async.commit_group;" ::: "memory")
#define CP_WAIT0()  asm volatile("cp.async.wait_group 0;" ::: "memory")

__device__ __forceinline__ void mma16n8k8(float* c, const uint32_t* a, const uint32_t* b) {
    asm volatile("mma.sync.aligned.m16n8k8.row.col.f32.tf32.tf32.f32 "
        "{%0,%1,%2,%3}, {%4,%5,%6,%7}, {%8,%9}, {%0,%1,%2,%3};"
        : "+f"(c[0]), "+f"(c[1]), "+f"(c[2]), "+f"(c[3])
        : "r"(a[0]), "r"(a[1]), "r"(a[2]), "r"(a[3]), "r"(b[0]), "r"(b[1]));
}

__device__ __forceinline__ void atomicMaxF(float* addr, float v) {
    if (v >= 0.f) atomicMax((int*)addr, __float_as_int(v));
    else          atomicMin((unsigned int*)addr, __float_as_uint(v));
}

// ---------------- setup kernels ----------------
__global__ void init_cnt() {
    int i = blockIdx.x * blockDim.x + threadIdx.x;
    if (i < SVOX) g_cnt[i] = 0;
}

__global__ void keys_kernel(const int* __restrict__ xy) {
    int p = blockIdx.x * blockDim.x + threadIdx.x;
    if (p < PTS) {
        int x = xy[2 * p], y = xy[2 * p + 1];
        int key = ((p >> 16) << 16) | (x << 8) | y;
        g_keys[p] = key;
        atomicAdd(&g_cnt[key], 1);
    }
}

// init pooled rows to -inf only where cnt >= 2 (cnt==1 rows get fully overwritten)
__global__ void __launch_bounds__(256) init_pooled() {
    int v = blockIdx.x * 8 + (threadIdx.x >> 5);
    int lane = threadIdx.x & 31;
    if (g_cnt[v] < 2) return;
    float4 neg = make_float4(NEGINF, NEGINF, NEGINF, NEGINF);
    float4* row = (float4*)(g_pooled + (size_t)v * 512);
#pragma unroll
    for (int i = 0; i < 4; i++) row[lane + 32 * i] = neg;
}

__global__ void roundW(const float* __restrict__ W, float* __restrict__ Wr, int n) {
    int i = blockIdx.x * blockDim.x + threadIdx.x;
    if (i < n) Wr[i] = to_tf32(W[i]);
}

// ---------------- column stats ----------------
template <int C>
__global__ void __launch_bounds__(256) stats_part(const float* __restrict__ Y) {
    const int PER = 256 / C;
    int t = threadIdx.x;
    int c = t % C, sl = t / C;
    int r0 = blockIdx.x * (PTS / 256);
    float s = 0.f, q = 0.f;
    for (int r = r0 + sl; r < r0 + PTS / 256; r += PER) {
        float v = Y[(size_t)r * C + c];
        s += v; q += v * v;
    }
    __shared__ float ss[256], sq[256];
    ss[t] = s; sq[t] = q;
    __syncthreads();
    if (sl == 0) {
        for (int i = 1; i < PER; i++) { s += ss[c + i * C]; q += sq[c + i * C]; }
        g_part[blockIdx.x * 2 * C + c]     = s;
        g_part[blockIdx.x * 2 * C + C + c] = q;
    }
}

template <int C>
__global__ void __launch_bounds__(256) stats_fin(int L, const float* __restrict__ gam,
                                                 const float* __restrict__ bet) {
    int c = blockIdx.x * 8 + (threadIdx.x >> 5);
    int lane = threadIdx.x & 31;
    if (c >= C) return;
    float s = 0.f, q = 0.f;
#pragma unroll
    for (int b = lane; b < 256; b += 32) {
        s += g_part[b * 2 * C + c];
        q += g_part[b * 2 * C + C + c];
    }
#pragma unroll
    for (int o = 16; o; o >>= 1) {
        s += __shfl_down_sync(0xFFFFFFFFu, s, o);
        q += __shfl_down_sync(0xFFFFFFFFu, q, o);
    }
    if (lane == 0) {
        float mean = s / (float)PTS;
        float var  = q / (float)PTS - mean * mean;
        float sc   = gam[c] * rsqrtf(var + EPSV);
        g_scale[L][c] = sc;
        g_shift[L][c] = bet[c] - mean * sc;
    }
}

// ---------------- GEMM1 (K=8, FFMA, exact fp32) ----------------
__global__ void __launch_bounds__(256) gemm1(const float* __restrict__ X, const float* __restrict__ W) {
    __shared__ float Xs[128][9];
    __shared__ float Ws[8][64];
    int tid = threadIdx.x;
    int m0 = blockIdx.x * 128;
    int row = tid >> 1, c4 = (tid & 1) * 4;
    float4 xv = *(const float4*)(X + (size_t)(m0 + row) * 8 + c4);
    float xa[4] = {xv.x, xv.y, xv.z, xv.w};
#pragma unroll
    for (int j = 0; j < 4; j++)
        Xs[row][c4 + j] = xa[j] * g_scale[0][c4 + j] + g_shift[0][c4 + j];
    if (tid < 128) {
        int r = tid >> 4, cc = (tid & 15) * 4;
        *(float4*)&Ws[r][cc] = *(const float4*)(W + r * 64 + cc);
    }
    __syncthreads();
    int tx = tid & 15, ty = tid >> 4;
    float acc[8][4] = {};
#pragma unroll
    for (int k = 0; k < 8; k++) {
        float4 bv = *(float4*)&Ws[k][tx * 4];
        float b[4] = {bv.x, bv.y, bv.z, bv.w};
#pragma unroll
        for (int i = 0; i < 8; i++) {
            float a = Xs[ty * 8 + i][k];
#pragma unroll
            for (int j = 0; j < 4; j++) acc[i][j] += a * b[j];
        }
    }
#pragma unroll
    for (int i = 0; i < 8; i++) {
        float4 o = make_float4(acc[i][0], acc[i][1], acc[i][2], acc[i][3]);
        *(float4*)&g_Y1[(size_t)(m0 + ty * 8 + i) * 64 + tx * 4] = o;
    }
}

// ---------------- tf32 mma.sync GEMM ----------------
// Y[M,N] = relu(X*scale[L]+shift[L])[M,K] @ Wr[K,N]
// CTA: 128x128 tile, 8 warps (2x4), warp tile 64x32. BK=16 double-buffered.
template <int K, int NFULL, bool SCATTER>
__global__ void __launch_bounds__(256) hgemm(const float* __restrict__ X,
                                             const float* __restrict__ Wr,
                                             float* __restrict__ Y, int L) {
    __shared__ __align__(16) float As[2][16][136];   // [k][m], pad-136 -> conflict-free frags
    __shared__ __align__(16) float Bs[2][16][136];   // [k][n]
    const int S = K / 16;

    int tid = threadIdx.x;
    int wid = tid >> 5, lane = tid & 31;
    int warpM = wid & 1, warpN = wid >> 1;
    int gid = lane >> 2, tig = lane & 3;
    int m0 = blockIdx.x * 128;
    int n0 = blockIdx.y * 128;

    const float* scl = g_scale[L];
    const float* shf = g_shift[L];

    const int ar = tid >> 1;            // A row this thread stages
    const int ach = (tid & 1) * 8;      // A k-offset within chunk
    const int bk = tid >> 4;            // B k-row this thread copies
    const int bc = (tid & 15) * 8;      // B n-offset

    float areg[8];
    auto loadA = [&](int kc) {
        const float4* p = (const float4*)(X + (size_t)(m0 + ar) * K + kc + ach);
        float4 v0 = p[0], v1 = p[1];
        areg[0] = v0.x; areg[1] = v0.y; areg[2] = v0.z; areg[3] = v0.w;
        areg[4] = v1.x; areg[5] = v1.y; areg[6] = v1.z; areg[7] = v1.w;
    };
    auto storeA = [&](int buf, int kc) {
#pragma unroll
        for (int j = 0; j < 8; j++) {
            float v = fmaxf(areg[j] * scl[kc + ach + j] + shf[kc + ach + j], 0.f);
            As[buf][ach + j][ar] = to_tf32(v);
        }
    };
    auto cpB = [&](int buf, int kc) {
        const float* src = Wr + (size_t)(kc + bk) * NFULL + n0 + bc;
        uint32_t dst = smem_u32(&Bs[buf][bk][bc]);
        cp16(dst, src);
        cp16(dst + 16, src + 4);
        CP_COMMIT();
    };

    float acc[4][4][4] = {};

    // prologue
    loadA(0);
    cpB(0, 0);
    storeA(0, 0);
    CP_WAIT0();
    __syncthreads();

    for (int s = 0; s < S; s++) {
        int buf = s & 1;
        if (s + 1 < S) { cpB(buf ^ 1, (s + 1) * 16); loadA((s + 1) * 16); }

        // compute on buf
#pragma unroll
        for (int kk = 0; kk < 16; kk += 8) {
            uint32_t a[4][4], b[4][2];
#pragma unroll
            for (int mt = 0; mt < 4; mt++) {
                int rb = warpM * 64 + mt * 16 + gid;
                a[mt][0] = __float_as_uint(As[buf][kk + tig][rb]);
                a[mt][1] = __float_as_uint(As[buf][kk + tig][rb + 8]);
                a[mt][2] = __float_as_uint(As[buf][kk + tig + 4][rb]);
                a[mt][3] = __float_as_uint(As[buf][kk + tig + 4][rb + 8]);
            }
#pragma unroll
            for (int nt = 0; nt < 4; nt++) {
                int nb = warpN * 32 + nt * 8 + gid;
                b[nt][0] = __float_as_uint(Bs[buf][kk + tig][nb]);
                b[nt][1] = __float_as_uint(Bs[buf][kk + tig + 4][nb]);
            }
#pragma unroll
            for (int mt = 0; mt < 4; mt++)
#pragma unroll
                for (int nt = 0; nt < 4; nt++)
                    mma16n8k8(acc[mt][nt], a[mt], b[nt]);
        }

        if (s + 1 < S) { storeA(buf ^ 1, (s + 1) * 16); CP_WAIT0(); }
        __syncthreads();
    }

    // ---- epilogue ----
    // D frag: c0=(row gid, col 2tig) c1=(gid, 2tig+1) c2=(gid+8, 2tig) c3=(gid+8, 2tig+1)
#pragma unroll
    for (int mt = 0; mt < 4; mt++) {
#pragma unroll
        for (int half = 0; half < 2; half++) {
            int m = m0 + warpM * 64 + mt * 16 + gid + 8 * half;
            if (!SCATTER) {
                float* yrow = Y + (size_t)m * NFULL + n0;
#pragma unroll
                for (int nt = 0; nt < 4; nt++) {
                    int n = warpN * 32 + nt * 8 + 2 * tig;
                    float2 o = make_float2(acc[mt][nt][2 * half], acc[mt][nt][2 * half + 1]);
                    *(float2*)(yrow + n) = o;
                }
            } else {
                int key = g_keys[m];
                int cnt = g_cnt[key];
                float* prow = g_pooled + (size_t)key * 512 + n0;
                if (cnt == 1) {
#pragma unroll
                    for (int nt = 0; nt < 4; nt++) {
                        int n = warpN * 32 + nt * 8 + 2 * tig;
                        float2 o = make_float2(acc[mt][nt][2 * half], acc[mt][nt][2 * half + 1]);
                        *(float2*)(prow + n) = o;
                    }
                } else {
#pragma unroll
                    for (int nt = 0; nt < 4; nt++) {
                        int n = warpN * 32 + nt * 8 + 2 * tig;
                        atomicMaxF(prow + n, acc[mt][nt][2 * half]);
                        atomicMaxF(prow + n + 1, acc[mt][nt][2 * half + 1]);
                    }
                }
            }
        }
    }
}

// ---------------- output: comp = relu(pooled @ Wc) masked, transposed ----------------
__global__ void __launch_bounds__(256) outker(const float* __restrict__ Wc, float* __restrict__ out) {
    __shared__ float sm[32][129];
    __shared__ int scnt[32];
    int tid = threadIdx.x;
    int vbase = blockIdx.x * 32;
    int vi = tid & 31, cg = tid >> 5;
    if (tid < 32) scnt[tid] = g_cnt[vbase + tid];
    __syncthreads();
    float acc[4] = {0.f, 0.f, 0.f, 0.f};

    for (int kc = 0; kc < 512; kc += 128) {
#pragma unroll
        for (int i = 0; i < 4; i++) {
            int q = tid + 256 * i;
            int row = q >> 5, col = (q & 31) * 4;
            if (scnt[row]) {
                float4 v = *(const float4*)(g_pooled + (size_t)(vbase + row) * 512 + kc + col);
                sm[row][col + 0] = v.x; sm[row][col + 1] = v.y;
                sm[row][col + 2] = v.z; sm[row][col + 3] = v.w;
            } else {
                sm[row][col + 0] = 0.f; sm[row][col + 1] = 0.f;
                sm[row][col + 2] = 0.f; sm[row][col + 3] = 0.f;
            }
        }
        __syncthreads();
#pragma unroll 4
        for (int k = 0; k < 128; k++) {
            float p = sm[vi][k];
            float4 w = *(const float4*)(Wc + (size_t)(kc + k) * 32 + cg * 4);
            acc[0] += p * w.x; acc[1] += p * w.y; acc[2] += p * w.z; acc[3] += p * w.w;
        }
        __syncthreads();
    }

    int v = vbase + vi;
    bool oc = scnt[vi] > 0;
    int b = v >> 16, hw = v & 65535;
#pragma unroll
    for (int j = 0; j < 4; j++) {
        float r = oc ? fmaxf(acc[j], 0.f) : 0.f;
        out[(size_t)(b * 32 + cg * 4 + j) * 65536 + hw] = r;
    }
}

// ---------------- launcher ----------------
extern "C" void kernel_launch(void* const* d_in, const int* in_sizes, int n_in,
                              void* d_out, int out_size) {
    (void)in_sizes; (void)n_in; (void)out_size;
    const float* pt_fea = (const float*)d_in[0];
    const float* bn0_g  = (const float*)d_in[1];
    const float* bn0_b  = (const float*)d_in[2];
    const float* W1     = (const float*)d_in[3];
    const float* bn1_g  = (const float*)d_in[4];
    const float* bn1_b  = (const float*)d_in[5];
    const float* W2     = (const float*)d_in[6];
    const float* bn2_g  = (const float*)d_in[7];
    const float* bn2_b  = (const float*)d_in[8];
    const float* W3     = (const float*)d_in[9];
    const float* bn3_g  = (const float*)d_in[10];
    const float* bn3_b  = (const float*)d_in[11];
    const float* W4     = (const float*)d_in[12];
    const float* Wc     = (const float*)d_in[13];
    const int*   xy     = (const int*)d_in[14];
    float* out = (float*)d_out;

    float *Y1p, *Y2p, *Y3p, *Wr2p, *Wr3p, *Wr4p;
    cudaGetSymbolAddress((void**)&Y1p, g_Y1);
    cudaGetSymbolAddress((void**)&Y2p, g_Y2);
    cudaGetSymbolAddress((void**)&Y3p, g_Y3);
    cudaGetSymbolAddress((void**)&Wr2p, g_Wr2);
    cudaGetSymbolAddress((void**)&Wr3p, g_Wr3);
    cudaGetSymbolAddress((void**)&Wr4p, g_Wr4);

    init_cnt<<<512, 256>>>();
    keys_kernel<<<512, 256>>>(xy);
    init_pooled<<<16384, 256>>>();

    roundW<<<(64 * 128 + 255) / 256, 256>>>(W2, Wr2p, 64 * 128);
    roundW<<<(128 * 256 + 255) / 256, 256>>>(W3, Wr3p, 128 * 256);
    roundW<<<(256 * 512 + 255) / 256, 256>>>(W4, Wr4p, 256 * 512);

    stats_part<8><<<256, 256>>>(pt_fea);
    stats_fin<8><<<1, 256>>>(0, bn0_g, bn0_b);
    gemm1<<<1024, 256>>>(pt_fea, W1);

    stats_part<64><<<256, 256>>>(Y1p);
    stats_fin<64><<<8, 256>>>(1, bn1_g, bn1_b);
    hgemm<64, 128, false><<<dim3(1024, 1), 256>>>(Y1p, Wr2p, Y2p, 1);

    stats_part<128><<<256, 256>>>(Y2p);
    stats_fin<128><<<16, 256>>>(2, bn2_g, bn2_b);
    hgemm<128, 256, false><<<dim3(1024, 2), 256>>>(Y2p, Wr3p, Y3p, 2);

    stats_part<256><<<256, 256>>>(Y3p);
    stats_fin<256><<<32, 256>>>(3, bn3_g, bn3_b);
    hgemm<256, 512, true><<<dim3(1024, 4), 256>>>(Y3p, Wr4p, nullptr, 3);

    outker<<<4096, 256>>>(Wc, out);
}

// round 6
// speedup vs baseline: 1.9795x; 1.1566x over previous
#include <cuda_runtime.h>
#include <cstdint>

#define PTS 131072
#define SVOX 131072
#define EPSV 1e-5f
#define MAXP 16

// ---------------- static device scratch ----------------
__device__ float g_Y1[PTS * 64];
__device__ float g_Y2[PTS * 128];
__device__ float g_Y3[PTS * 256];
__device__ float g_Y4[67108864];          // [PTS, 512]
__device__ int   g_cnt[SVOX];
__device__ int   g_slot[SVOX * MAXP];
__device__ float g_part[1024 * 1024];     // per-CTA stats partials
__device__ float g_scale[4][256];
__device__ float g_shift[4][256];
__device__ float g_Wr2[64 * 128];         // tf32-rounded weights [K][N]
__device__ float g_Wr3[128 * 256];
__device__ float g_Wr4[256 * 512];

// ---------------- helpers ----------------
__device__ __forceinline__ uint32_t smem_u32(const void* p) {
    uint32_t a;
    asm("{ .reg .u64 t; cvta.to.shared.u64 t, %1; cvt.u32.u64 %0, t; }" : "=r"(a) : "l"(p));
    return a;
}
__device__ __forceinline__ float to_tf32(float x) {
    uint32_t o; asm("cvt.rna.tf32.f32 %0, %1;" : "=r"(o) : "f"(x));
    return __uint_as_float(o);
}
__device__ __forceinline__ void cp16(uint32_t saddr, const void* g) {
    asm volatile("cp.async.cg.shared.global [%0], [%1], 16;" :: "r"(saddr), "l"(g));
}
#define CP_COMMIT() asm volatile("cp.async.commit_group;" ::: "memory")
#define CP_WAIT0()  asm volatile("cp.async.wait_group 0;" ::: "memory")

__device__ __forceinline__ void mma16n8k8(float* c, const uint32_t* a, const uint32_t* b) {
    asm volatile("mma.sync.aligned.m16n8k8.row.col.f32.tf32.tf32.f32 "
        "{%0,%1,%2,%3}, {%4,%5,%6,%7}, {%8,%9}, {%0,%1,%2,%3};"
        : "+f"(c[0]), "+f"(c[1]), "+f"(c[2]), "+f"(c[3])
        : "r"(a[0]), "r"(a[1]), "r"(a[2]), "r"(a[3]), "r"(b[0]), "r"(b[1]));
}

// ---------------- setup kernels ----------------
__global__ void init_cnt() {
    int i = blockIdx.x * blockDim.x + threadIdx.x;
    if (i < SVOX) g_cnt[i] = 0;
}

__global__ void keys_kernel(const int* __restrict__ xy) {
    int p = blockIdx.x * blockDim.x + threadIdx.x;
    if (p < PTS) {
        int x = xy[2 * p], y = xy[2 * p + 1];
        int key = ((p >> 16) << 16) | (x << 8) | y;
        int rank = atomicAdd(&g_cnt[key], 1);
        if (rank < MAXP) g_slot[key * MAXP + rank] = p;
    }
}

__global__ void roundW(const float* __restrict__ W, float* __restrict__ Wr, int n) {
    int i = blockIdx.x * blockDim.x + threadIdx.x;
    if (i < n) Wr[i] = to_tf32(W[i]);
}

// ---------------- input stats (C=8 only; later layers fused into GEMMs) ----------------
__global__ void __launch_bounds__(256) stats_part8(const float* __restrict__ Y) {
    const int C = 8, PER = 32;
    int t = threadIdx.x;
    int c = t % C, sl = t / C;
    int r0 = blockIdx.x * (PTS / 256);
    float s = 0.f, q = 0.f;
    for (int r = r0 + sl; r < r0 + PTS / 256; r += PER) {
        float v = Y[(size_t)r * C + c];
        s += v; q += v * v;
    }
    __shared__ float ss[256], sq[256];
    ss[t] = s; sq[t] = q;
    __syncthreads();
    if (sl == 0) {
        for (int i = 1; i < PER; i++) { s += ss[c + i * C]; q += sq[c + i * C]; }
        g_part[(blockIdx.x * 2) * C + c]     = s;
        g_part[(blockIdx.x * 2 + 1) * C + c] = q;
    }
}

template <int C, int NP>
__global__ void __launch_bounds__(256) stats_fin(int L, const float* __restrict__ gam,
                                                 const float* __restrict__ bet) {
    int c = blockIdx.x * 8 + (threadIdx.x >> 5);
    int lane = threadIdx.x & 31;
    if (c >= C) return;
    float s = 0.f, q = 0.f;
    for (int b = lane; b < NP; b += 32) {
        s += g_part[(b * 2) * C + c];
        q += g_part[(b * 2 + 1) * C + c];
    }
#pragma unroll
    for (int o = 16; o; o >>= 1) {
        s += __shfl_down_sync(0xFFFFFFFFu, s, o);
        q += __shfl_down_sync(0xFFFFFFFFu, q, o);
    }
    if (lane == 0) {
        float mean = s / (float)PTS;
        float var  = q / (float)PTS - mean * mean;
        float sc   = gam[c] * rsqrtf(var + EPSV);
        g_scale[L][c] = sc;
        g_shift[L][c] = bet[c] - mean * sc;
    }
}

// ---------------- GEMM1 (K=8, FFMA, exact fp32) + fused Y1 stats ----------------
__global__ void __launch_bounds__(256) gemm1(const float* __restrict__ X, const float* __restrict__ W) {
    __shared__ float Xs[128][9];
    __shared__ float Ws[8][64];
    __shared__ float s1[16][68], q1[16][68];
    int tid = threadIdx.x;
    int m0 = blockIdx.x * 128;
    int row = tid >> 1, c4 = (tid & 1) * 4;
    float4 xv = *(const float4*)(X + (size_t)(m0 + row) * 8 + c4);
    float xa[4] = {xv.x, xv.y, xv.z, xv.w};
#pragma unroll
    for (int j = 0; j < 4; j++)
        Xs[row][c4 + j] = xa[j] * g_scale[0][c4 + j] + g_shift[0][c4 + j];
    if (tid < 128) {
        int r = tid >> 4, cc = (tid & 15) * 4;
        *(float4*)&Ws[r][cc] = *(const float4*)(W + r * 64 + cc);
    }
    __syncthreads();
    int tx = tid & 15, ty = tid >> 4;
    float acc[8][4] = {};
#pragma unroll
    for (int k = 0; k < 8; k++) {
        float4 bv = *(float4*)&Ws[k][tx * 4];
        float b[4] = {bv.x, bv.y, bv.z, bv.w};
#pragma unroll
        for (int i = 0; i < 8; i++) {
            float a = Xs[ty * 8 + i][k];
#pragma unroll
            for (int j = 0; j < 4; j++) acc[i][j] += a * b[j];
        }
    }
#pragma unroll
    for (int i = 0; i < 8; i++) {
        float4 o = make_float4(acc[i][0], acc[i][1], acc[i][2], acc[i][3]);
        *(float4*)&g_Y1[(size_t)(m0 + ty * 8 + i) * 64 + tx * 4] = o;
    }
    // fused column stats (raw Y1)
#pragma unroll
    for (int j = 0; j < 4; j++) {
        float s = 0.f, q = 0.f;
#pragma unroll
        for (int i = 0; i < 8; i++) { float v = acc[i][j]; s += v; q += v * v; }
        s1[ty][tx * 4 + j] = s;
        q1[ty][tx * 4 + j] = q;
    }
    __syncthreads();
    if (tid < 64) {
        float S = 0.f, Q = 0.f;
#pragma unroll
        for (int t = 0; t < 16; t++) { S += s1[t][tid]; Q += q1[t][tid]; }
        g_part[(blockIdx.x * 2) * 64 + tid]     = S;
        g_part[(blockIdx.x * 2 + 1) * 64 + tid] = Q;
    }
}

// ---------------- tf32 mma.sync GEMM (optionally fused column stats) ----------------
// Y[M,N] = relu(X*scale[L]+shift[L])[M,K] @ Wr[K,N]
// CTA: 128x128 tile, 8 warps (2x4), warp tile 64x32. BK=16 double-buffered.
template <int K, int NFULL, bool STATS>
__global__ void __launch_bounds__(256) hgemm(const float* __restrict__ X,
                                             const float* __restrict__ Wr,
                                             float* __restrict__ Y, int L) {
    __shared__ __align__(16) float As[2][16][136];
    __shared__ __align__(16) float Bs[2][16][136];
    __shared__ float ssum[2][4][32], ssq[2][4][32];
    const int S = K / 16;

    int tid = threadIdx.x;
    int wid = tid >> 5, lane = tid & 31;
    int warpM = wid & 1, warpN = wid >> 1;
    int gid = lane >> 2, tig = lane & 3;
    int m0 = blockIdx.x * 128;
    int n0 = blockIdx.y * 128;

    const float* scl = g_scale[L];
    const float* shf = g_shift[L];

    const int ar = tid >> 1;
    const int ach = (tid & 1) * 8;
    const int bk = tid >> 4;
    const int bc = (tid & 15) * 8;

    float areg[8];
    auto loadA = [&](int kc) {
        const float4* p = (const float4*)(X + (size_t)(m0 + ar) * K + kc + ach);
        float4 v0 = p[0], v1 = p[1];
        areg[0] = v0.x; areg[1] = v0.y; areg[2] = v0.z; areg[3] = v0.w;
        areg[4] = v1.x; areg[5] = v1.y; areg[6] = v1.z; areg[7] = v1.w;
    };
    auto storeA = [&](int buf, int kc) {
#pragma unroll
        for (int j = 0; j < 8; j++) {
            float v = fmaxf(areg[j] * scl[kc + ach + j] + shf[kc + ach + j], 0.f);
            As[buf][ach + j][ar] = to_tf32(v);
        }
    };
    auto cpB = [&](int buf, int kc) {
        const float* src = Wr + (size_t)(kc + bk) * NFULL + n0 + bc;
        uint32_t dst = smem_u32(&Bs[buf][bk][bc]);
        cp16(dst, src);
        cp16(dst + 16, src + 4);
        CP_COMMIT();
    };

    float acc[4][4][4] = {};

    loadA(0);
    cpB(0, 0);
    storeA(0, 0);
    CP_WAIT0();
    __syncthreads();

    for (int s = 0; s < S; s++) {
        int buf = s & 1;
        if (s + 1 < S) { cpB(buf ^ 1, (s + 1) * 16); loadA((s + 1) * 16); }

#pragma unroll
        for (int kk = 0; kk < 16; kk += 8) {
            uint32_t a[4][4], b[4][2];
#pragma unroll
            for (int mt = 0; mt < 4; mt++) {
                int rb = warpM * 64 + mt * 16 + gid;
                a[mt][0] = __float_as_uint(As[buf][kk + tig][rb]);
                a[mt][1] = __float_as_uint(As[buf][kk + tig][rb + 8]);
                a[mt][2] = __float_as_uint(As[buf][kk + tig + 4][rb]);
                a[mt][3] = __float_as_uint(As[buf][kk + tig + 4][rb + 8]);
            }
#pragma unroll
            for (int nt = 0; nt < 4; nt++) {
                int nb = warpN * 32 + nt * 8 + gid;
                b[nt][0] = __float_as_uint(Bs[buf][kk + tig][nb]);
                b[nt][1] = __float_as_uint(Bs[buf][kk + tig + 4][nb]);
            }
#pragma unroll
            for (int mt = 0; mt < 4; mt++)
#pragma unroll
                for (int nt = 0; nt < 4; nt++)
                    mma16n8k8(acc[mt][nt], a[mt], b[nt]);
        }

        if (s + 1 < S) { storeA(buf ^ 1, (s + 1) * 16); CP_WAIT0(); }
        __syncthreads();
    }

    // ---- Y store ----
#pragma unroll
    for (int mt = 0; mt < 4; mt++) {
#pragma unroll
        for (int half = 0; half < 2; half++) {
            int m = m0 + warpM * 64 + mt * 16 + gid + 8 * half;
            float* yrow = Y + (size_t)m * NFULL + n0;
#pragma unroll
            for (int nt = 0; nt < 4; nt++) {
                int n = warpN * 32 + nt * 8 + 2 * tig;
                float2 o = make_float2(acc[mt][nt][2 * half], acc[mt][nt][2 * half + 1]);
                *(float2*)(yrow + n) = o;
            }
        }
    }

    // ---- fused column stats (raw Y tile), deterministic ----
    if (STATS) {
        float s_[4][2] = {}, q_[4][2] = {};
#pragma unroll
        for (int nt = 0; nt < 4; nt++)
#pragma unroll
            for (int j = 0; j < 2; j++)
#pragma unroll
                for (int mt = 0; mt < 4; mt++)
#pragma unroll
                    for (int half = 0; half < 2; half++) {
                        float v = acc[mt][nt][2 * half + j];
                        s_[nt][j] += v; q_[nt][j] += v * v;
                    }
#pragma unroll
        for (int o = 16; o >= 4; o >>= 1)
#pragma unroll
            for (int nt = 0; nt < 4; nt++)
#pragma unroll
                for (int j = 0; j < 2; j++) {
                    s_[nt][j] += __shfl_down_sync(0xFFFFFFFFu, s_[nt][j], o);
                    q_[nt][j] += __shfl_down_sync(0xFFFFFFFFu, q_[nt][j], o);
                }
        if (lane < 4) {
#pragma unroll
            for (int nt = 0; nt < 4; nt++)
#pragma unroll
                for (int j = 0; j < 2; j++) {
                    ssum[warpM][warpN][nt * 8 + 2 * lane + j] = s_[nt][j];
                    ssq[warpM][warpN][nt * 8 + 2 * lane + j]  = q_[nt][j];
                }
        }
        __syncthreads();
        if (tid < 128) {
            int wN = tid >> 5, cl = tid & 31;
            float S2 = ssum[0][wN][cl] + ssum[1][wN][cl];
            float Q2 = ssq[0][wN][cl] + ssq[1][wN][cl];
            int col = n0 + wN * 32 + cl;
            g_part[(blockIdx.x * 2) * NFULL + col]     = S2;
            g_part[(blockIdx.x * 2 + 1) * NFULL + col] = Q2;
        }
    }
}

// ---------------- output: gather-max over voxel slots + relu(@Wc), transposed ----------------
__global__ void __launch_bounds__(256) outker(const float* __restrict__ Wc, float* __restrict__ out) {
    __shared__ float sm[32][129];
    __shared__ int scnt[32];
    __shared__ int sslot[32][MAXP];
    int tid = threadIdx.x;
    int vbase = blockIdx.x * 32;
    int vi = tid & 31, cg = tid >> 5;
    if (tid < 32) scnt[tid] = min(g_cnt[vbase + tid], MAXP);
    __syncthreads();
#pragma unroll
    for (int e = 0; e < 2; e++) {
        int idx = tid + 256 * e;
        int v = idx >> 4, s = idx & (MAXP - 1);
        if (s < scnt[v]) sslot[v][s] = g_slot[(vbase + v) * MAXP + s];
    }
    __syncthreads();

    float acc[4] = {0.f, 0.f, 0.f, 0.f};
    for (int kc = 0; kc < 512; kc += 128) {
#pragma unroll
        for (int i = 0; i < 4; i++) {
            int q = tid + 256 * i;
            int row = q >> 5, col = (q & 31) * 4;
            int cn = scnt[row];
            float4 mx = make_float4(0.f, 0.f, 0.f, 0.f);
            if (cn > 0) {
                mx = *(const float4*)(g_Y4 + (size_t)sslot[row][0] * 512 + kc + col);
                for (int j = 1; j < cn; j++) {
                    float4 t = *(const float4*)(g_Y4 + (size_t)sslot[row][j] * 512 + kc + col);
                    mx.x = fmaxf(mx.x, t.x); mx.y = fmaxf(mx.y, t.y);
                    mx.z = fmaxf(mx.z, t.z); mx.w = fmaxf(mx.w, t.w);
                }
            }
            sm[row][col + 0] = mx.x; sm[row][col + 1] = mx.y;
            sm[row][col + 2] = mx.z; sm[row][col + 3] = mx.w;
        }
        __syncthreads();
#pragma unroll 4
        for (int k = 0; k < 128; k++) {
            float p = sm[vi][k];
            float4 w = *(const float4*)(Wc + (size_t)(kc + k) * 32 + cg * 4);
            acc[0] += p * w.x; acc[1] += p * w.y; acc[2] += p * w.z; acc[3] += p * w.w;
        }
        __syncthreads();
    }

    int v = vbase + vi;
    bool oc = scnt[vi] > 0;
    int b = v >> 16, hw = v & 65535;
#pragma unroll
    for (int j = 0; j < 4; j++) {
        float r = oc ? fmaxf(acc[j], 0.f) : 0.f;
        out[(size_t)(b * 32 + cg * 4 + j) * 65536 + hw] = r;
    }
}

// ---------------- launcher ----------------
extern "C" void kernel_launch(void* const* d_in, const int* in_sizes, int n_in,
                              void* d_out, int out_size) {
    (void)in_sizes; (void)n_in; (void)out_size;
    const float* pt_fea = (const float*)d_in[0];
    const float* bn0_g  = (const float*)d_in[1];
    const float* bn0_b  = (const float*)d_in[2];
    const float* W1     = (const float*)d_in[3];
    const float* bn1_g  = (const float*)d_in[4];
    const float* bn1_b  = (const float*)d_in[5];
    const float* W2     = (const float*)d_in[6];
    const float* bn2_g  = (const float*)d_in[7];
    const float* bn2_b  = (const float*)d_in[8];
    const float* W3     = (const float*)d_in[9];
    const float* bn3_g  = (const float*)d_in[10];
    const float* bn3_b  = (const float*)d_in[11];
    const float* W4     = (const float*)d_in[12];
    const float* Wc     = (const float*)d_in[13];
    const int*   xy     = (const int*)d_in[14];
    float* out = (float*)d_out;

    float *Y1p, *Y2p, *Y3p, *Y4p, *Wr2p, *Wr3p, *Wr4p;
    cudaGetSymbolAddress((void**)&Y1p, g_Y1);
    cudaGetSymbolAddress((void**)&Y2p, g_Y2);
    cudaGetSymbolAddress((void**)&Y3p, g_Y3);
    cudaGetSymbolAddress((void**)&Y4p, g_Y4);
    cudaGetSymbolAddress((void**)&Wr2p, g_Wr2);
    cudaGetSymbolAddress((void**)&Wr3p, g_Wr3);
    cudaGetSymbolAddress((void**)&Wr4p, g_Wr4);

    init_cnt<<<512, 256>>>();
    keys_kernel<<<512, 256>>>(xy);

    roundW<<<(64 * 128 + 255) / 256, 256>>>(W2, Wr2p, 64 * 128);
    roundW<<<(128 * 256 + 255) / 256, 256>>>(W3, Wr3p, 128 * 256);
    roundW<<<(256 * 512 + 255) / 256, 256>>>(W4, Wr4p, 256 * 512);

    stats_part8<<<256, 256>>>(pt_fea);
    stats_fin<8, 256><<<1, 256>>>(0, bn0_g, bn0_b);

    gemm1<<<1024, 256>>>(pt_fea, W1);
    stats_fin<64, 1024><<<8, 256>>>(1, bn1_g, bn1_b);

    hgemm<64, 128, true><<<dim3(1024, 1), 256>>>(Y1p, Wr2p, Y2p, 1);
    stats_fin<128, 1024><<<16, 256>>>(2, bn2_g, bn2_b);

    hgemm<128, 256, true><<<dim3(1024, 2), 256>>>(Y2p, Wr3p, Y3p, 2);
    stats_fin<256, 1024><<<32, 256>>>(3, bn3_g, bn3_b);

    hgemm<256, 512, false><<<dim3(1024, 4), 256>>>(Y3p, Wr4p, Y4p, 3);

    outker<<<4096, 256>>>(Wc, out);
}